// round 6
// baseline (speedup 1.0000x reference)
#include <cuda_runtime.h>
#include <cstdint>

// Problem constants
#define BATCHN 128
#define GS 7
#define NB 2
#define NC 20
#define CH 30
#define CELLS (BATCHN * GS * GS)      // 6272
#define NTOT (CELLS * NB)             // 12544
#define PER_BATCH (GS * GS * NB)      // 98
#define THR_NMS 0.3f

// rank kernel layout: 256-thread blocks; valid region = NTOT/8 warps worst case
#define RWB 256
#define NVBLK (NTOT / 8 / 8)          // 196 valid blocks (8 warps each)
#define NIBLK (NTOT / RWB)            // 49 invalid blocks

typedef unsigned long long u64;

// ---------------- device scratch (static; no cudaMalloc) ---------------------
__device__ __align__(16) u64 g_vkeys[NTOT];   // compacted valid keys (any order)
__device__ float4 g_box[NTOT];
__device__ float4 g_pay[NTOT];        // (score, label, keep, 0)
__device__ int g_cnt[BATCHN];         // valid count per batch
__device__ u64 g_vmask[BATCHN * 2];   // validity bitmask per batch (98 bits)
__device__ int g_vtotal;              // atomic compaction counter (memset to 0)

// sigmoid matching XLA-GPU exp-based logistic: 1/(1+__nv_expf(-x)), div.rn
__device__ __forceinline__ float sigmoidf(float x) {
    return 1.0f / (1.0f + expf(-x));
}

__device__ __forceinline__ unsigned f2sortable(float f) {
    unsigned b = __float_as_uint(f);
    return (b & 0x80000000u) ? ~b : (b | 0x80000000u);
}

// ============ A) fused decode + parallel local rank + NMS + compaction =======
__global__ void __launch_bounds__(128) decode_nms_kernel(const float* __restrict__ p) {
    __shared__ float s_dec[GS * GS * CH];        // 1470 decoded values
    __shared__ u64 s_key[PER_BATCH];
    __shared__ float4 s_nbox[PER_BATCH];
    __shared__ unsigned char s_nlab[PER_BATCH];
    __shared__ unsigned char s_nloc[PER_BATCH];
    __shared__ unsigned char s_keep[PER_BATCH];
    __shared__ unsigned s_adj[PER_BATCH][4];     // suppression bitmask rows
    __shared__ unsigned s_supw[4];
    __shared__ unsigned s_wb[4];
    __shared__ int s_cnt;
    __shared__ int s_base;

    int tid = threadIdx.x;
    int b = blockIdx.x;

    // Phase 0: cooperative sigmoid decode (w,h channels raw)
    const float* pb = p + (size_t)b * (GS * GS * CH);
    for (int i = tid; i < GS * GS * CH; i += 128) {
        int c = i % CH;
        float x = pb[i];
        bool raw = (c == 2) | (c == 3) | (c == 6) | (c == 7);
        s_dec[i] = raw ? x : sigmoidf(x);
    }
    // zero adjacency rows while waiting
    if (tid < PER_BATCH) {
        s_adj[tid][0] = 0; s_adj[tid][1] = 0; s_adj[tid][2] = 0; s_adj[tid][3] = 0;
        s_keep[tid] = 0;
    }
    __syncthreads();

    // Phase 1: per-box decode (one thread per box)
    bool valid = false;
    u64 mykey = 0;
    float4 mybox;
    float myconf = 0.0f;
    unsigned char mylab = 0;
    if (tid < PER_BATCH) {
        int cell = tid >> 1;
        int bb = tid & 1;
        int gy = cell / GS, gx = cell % GS;
        const float* d = s_dec + cell * CH;

        float best = d[8 + NB + 0];
        int bi = 0;
#pragma unroll
        for (int c = 1; c < NC; c++) {
            float v = d[8 + NB + c];
            if (v > best) { best = v; bi = c; }
        }
        mylab = (unsigned char)(bi + 1);

        myconf = d[8 + bb];
        valid = myconf > 0.5f;
        float sx = d[bb * 4 + 0];
        float sy = d[bb * 4 + 1];
        float w = d[bb * 4 + 2];
        float h = d[bb * 4 + 3];
        float cx = (sx + (float)gx) / 7.0f;
        float cy = (sy + (float)gy) / 7.0f;
        mybox.x = cx - w / 2.0f;
        mybox.y = cy - h / 2.0f;
        mybox.z = cx + w / 2.0f;
        mybox.w = cy + h / 2.0f;

        int n = b * PER_BATCH + tid;
        g_box[n] = mybox;
        float keyf = valid ? myconf : __int_as_float(0xff800000);   // -inf
        mykey = ((u64)f2sortable(keyf) << 32) | (unsigned)n;
        s_key[tid] = mykey;
    }
    unsigned wb = __ballot_sync(0xffffffffu, valid);
    if ((tid & 31) == 0) s_wb[tid >> 5] = wb;
    __syncthreads();
    if (tid == 0) {
        u64 m0 = (u64)s_wb[0] | ((u64)s_wb[1] << 32);
        u64 m1 = (u64)s_wb[2] | ((u64)s_wb[3] << 32);
        g_vmask[2 * b] = m0;
        g_vmask[2 * b + 1] = m1;
        int cnt = __popcll(m0) + __popcll(m1);
        s_cnt = cnt;
        g_cnt[b] = cnt;
        s_base = atomicAdd(&g_vtotal, cnt);
    }
    __syncthreads();

    // Phase 2: parallel local rank (valid keys outrank all invalid; keys unique)
    if (tid < PER_BATCH && valid) {
        int r = 0;
#pragma unroll 7
        for (int j = 0; j < PER_BATCH; j++)
            r += (s_key[j] > mykey);
        // scatter into NMS working arrays + compacted export (rank ∈ [0,cnt))
        s_nbox[r] = mybox;
        s_nlab[r] = mylab;
        s_nloc[r] = (unsigned char)tid;
        g_vkeys[s_base + r] = mykey;
    }
    __syncthreads();

    int cnt = s_cnt;

    // Phase 3: parallel pairwise IoU -> adjacency bits (one j per thread per i)
    for (int i = 0; i < cnt - 1; i++) {
        int j = i + 1 + tid;
        if (j < cnt && s_nlab[i] == s_nlab[j]) {
            float4 bi = s_nbox[i];
            float4 bj = s_nbox[j];
            float ltx = fmaxf(bi.x, bj.x);
            float lty = fmaxf(bi.y, bj.y);
            float rbx = fminf(bi.z, bj.z);
            float rby = fminf(bi.w, bj.w);
            float iw = fmaxf(rbx - ltx, 0.0f);
            float ih = fmaxf(rby - lty, 0.0f);
            float inter = iw * ih;
            float ai = (bi.z - bi.x) * (bi.w - bi.y);
            float aj = (bj.z - bj.x) * (bj.w - bj.y);
            float uni = ai + aj - inter;
            float iou = inter / fmaxf(uni, 1e-9f);
            if (iou > THR_NMS)
                atomicOr(&s_adj[i][j >> 5], 1u << (j & 31));
        }
    }
    __syncthreads();

    // Phase 4: greedy scan over bitmask (single thread, register accumulators)
    if (tid == 0) {
        unsigned sw0 = 0, sw1 = 0, sw2 = 0, sw3 = 0;
        for (int i = 0; i < cnt; i++) {
            unsigned mybit;
            switch (i >> 5) {
                case 0: mybit = (sw0 >> (i & 31)) & 1u; break;
                case 1: mybit = (sw1 >> (i & 31)) & 1u; break;
                case 2: mybit = (sw2 >> (i & 31)) & 1u; break;
                default: mybit = (sw3 >> (i & 31)) & 1u; break;
            }
            if (!mybit) {
                sw0 |= s_adj[i][0];
                sw1 |= s_adj[i][1];
                sw2 |= s_adj[i][2];
                sw3 |= s_adj[i][3];
            }
        }
        s_supw[0] = sw0; s_supw[1] = sw1; s_supw[2] = sw2; s_supw[3] = sw3;
    }
    __syncthreads();

    for (int i = tid; i < cnt; i += 128) {
        if (!((s_supw[i >> 5] >> (i & 31)) & 1u))
            s_keep[s_nloc[i]] = 1;
    }
    __syncthreads();

    // Phase 5: payload write
    if (tid < PER_BATCH) {
        int n = b * PER_BATCH + tid;
        g_pay[n] = make_float4(myconf, (float)mylab,
                               s_keep[tid] ? 1.0f : 0.0f, 0.0f);
    }
}

// ============ B) fused valid-rank + invalid-write ============================
// blocks [0, NVBLK): warp-per-8-elements brute-force rank, no smem/barriers
// blocks [NVBLK, NVBLK+NIBLK): invalid elements, O(1) rank each
__global__ void __launch_bounds__(RWB) rank_write_kernel(float* __restrict__ out) {
    int blk = blockIdx.x;
    int tid = threadIdx.x;

    if (blk < NVBLK) {
        int V = g_vtotal;
        int gw = blk * 8 + (tid >> 5);      // global warp id
        int eBase = gw * 8;
        if (eBase >= V) return;
        int lane = tid & 31;

        // my 8 keys (broadcast loads, clamped)
        u64 mk0 = g_vkeys[min(eBase + 0, V - 1)];
        u64 mk1 = g_vkeys[min(eBase + 1, V - 1)];
        u64 mk2 = g_vkeys[min(eBase + 2, V - 1)];
        u64 mk3 = g_vkeys[min(eBase + 3, V - 1)];
        u64 mk4 = g_vkeys[min(eBase + 4, V - 1)];
        u64 mk5 = g_vkeys[min(eBase + 5, V - 1)];
        u64 mk6 = g_vkeys[min(eBase + 6, V - 1)];
        u64 mk7 = g_vkeys[min(eBase + 7, V - 1)];

        int c0 = 0, c1 = 0, c2 = 0, c3 = 0, c4 = 0, c5 = 0, c6 = 0, c7 = 0;
        int nv2 = V >> 1;                   // full ulonglong2 count
        const ulonglong2* vk2 = (const ulonglong2*)g_vkeys;
#pragma unroll 2
        for (int i2 = lane; i2 < nv2; i2 += 32) {
            ulonglong2 v = vk2[i2];
            c0 += (v.x > mk0) + (v.y > mk0);
            c1 += (v.x > mk1) + (v.y > mk1);
            c2 += (v.x > mk2) + (v.y > mk2);
            c3 += (v.x > mk3) + (v.y > mk3);
            c4 += (v.x > mk4) + (v.y > mk4);
            c5 += (v.x > mk5) + (v.y > mk5);
            c6 += (v.x > mk6) + (v.y > mk6);
            c7 += (v.x > mk7) + (v.y > mk7);
        }
        if ((V & 1) && lane == 0) {         // odd tail key
            u64 v = g_vkeys[V - 1];
            c0 += (v > mk0); c1 += (v > mk1); c2 += (v > mk2); c3 += (v > mk3);
            c4 += (v > mk4); c5 += (v > mk5); c6 += (v > mk6); c7 += (v > mk7);
        }
#pragma unroll
        for (int d = 16; d >= 1; d >>= 1) {
            c0 += __shfl_xor_sync(0xffffffffu, c0, d);
            c1 += __shfl_xor_sync(0xffffffffu, c1, d);
            c2 += __shfl_xor_sync(0xffffffffu, c2, d);
            c3 += __shfl_xor_sync(0xffffffffu, c3, d);
            c4 += __shfl_xor_sync(0xffffffffu, c4, d);
            c5 += __shfl_xor_sync(0xffffffffu, c5, d);
            c6 += __shfl_xor_sync(0xffffffffu, c6, d);
            c7 += __shfl_xor_sync(0xffffffffu, c7, d);
        }
        if (lane < 8 && eBase + lane < V) {
            int rank;
            u64 mykey;
            switch (lane) {
                case 0: rank = c0; mykey = mk0; break;
                case 1: rank = c1; mykey = mk1; break;
                case 2: rank = c2; mykey = mk2; break;
                case 3: rank = c3; mykey = mk3; break;
                case 4: rank = c4; mykey = mk4; break;
                case 5: rank = c5; mykey = mk5; break;
                case 6: rank = c6; mykey = mk6; break;
                default: rank = c7; mykey = mk7; break;
            }
            unsigned idx = (unsigned)(mykey & 0xffffffffu);
            float4 bx = g_box[idx];
            float4 pay = g_pay[idx];
            out[rank] = (float)(idx / PER_BATCH);
            *(float4*)(out + NTOT + 4 * rank) = bx;
            out[5 * NTOT + rank] = pay.y;   // label
            out[6 * NTOT + rank] = pay.x;   // score
            out[7 * NTOT + rank] = pay.z;   // keep
        }
    } else {
        __shared__ int s_incl[BATCHN];
        __shared__ int s_ws[4];
        int lane = tid & 31;

        // in-block inclusive scan of g_cnt[0..127] using first 128 threads
        if (tid < BATCHN) {
            int x = g_cnt[tid];
#pragma unroll
            for (int d = 1; d < 32; d <<= 1) {
                int y = __shfl_up_sync(0xffffffffu, x, d);
                if (lane >= d) x += y;
            }
            if (lane == 31) s_ws[tid >> 5] = x;
            s_incl[tid] = x;                 // partial; fixed below
        }
        __syncthreads();
        if (tid == 0) {
            int a = 0;
#pragma unroll
            for (int w = 0; w < 4; w++) { int t = s_ws[w]; s_ws[w] = a; a += t; }
        }
        __syncthreads();
        if (tid < BATCHN) s_incl[tid] += s_ws[tid >> 5];
        __syncthreads();

        int V = s_incl[BATCHN - 1];
        int n = (blk - NVBLK) * RWB + tid;   // 49*256 == NTOT exactly
        int b = n / PER_BATCH;
        int local = n - b * PER_BATCH;
        u64 m0 = g_vmask[2 * b];
        u64 m1 = g_vmask[2 * b + 1];
        bool valid = (local < 64) ? ((m0 >> local) & 1ULL)
                                  : ((m1 >> (local - 64)) & 1ULL);
        if (valid) return;                   // handled by valid path

        u64 i0 = ~m0;
        u64 i1 = (~m1) & ((1ULL << (PER_BATCH - 64)) - 1);
        int after;
        if (local < 64) {
            u64 hi = (local == 63) ? 0ULL : (i0 >> (local + 1));
            after = __popcll(hi) + __popcll(i1);
        } else {
            after = __popcll(i1 >> (local - 63));
        }
        int invafter = (NTOT - V) - (PER_BATCH * (b + 1) - s_incl[b]);
        int rank = V + invafter + after;

        float4 bx = g_box[n];
        float4 pay = g_pay[n];
        out[rank] = (float)b;
        *(float4*)(out + NTOT + 4 * rank) = bx;
        out[5 * NTOT + rank] = pay.y;
        out[6 * NTOT + rank] = pay.x;
        out[7 * NTOT + rank] = 0.0f;
    }
}

// ---------------- launch -----------------------------------------------------
extern "C" void kernel_launch(void* const* d_in, const int* in_sizes, int n_in,
                              void* d_out, int out_size) {
    const float* p = (const float*)d_in[0];
    float* out = (float*)d_out;

    void* vt = nullptr;
    cudaGetSymbolAddress(&vt, g_vtotal);
    cudaMemsetAsync(vt, 0, sizeof(int));

    decode_nms_kernel<<<BATCHN, 128>>>(p);
    rank_write_kernel<<<NVBLK + NIBLK, RWB>>>(out);
}

// round 7
// speedup vs baseline: 1.5240x; 1.5240x over previous
#include <cuda_runtime.h>
#include <cstdint>

// Problem constants
#define BATCHN 128
#define GS 7
#define NB 2
#define NC 20
#define CH 30
#define CELLS (BATCHN * GS * GS)      // 6272
#define NTOT (CELLS * NB)             // 12544
#define PER_BATCH (GS * GS * NB)      // 98
#define THR_NMS 0.3f

// rank kernel layout: 256-thread blocks, 8 warps, 4 elements per warp
#define RWB 256
#define ELW 4
#define NVBLK (NTOT / ELW / 8)        // 392 valid blocks (worst case V = NTOT)
#define NIBLK (NTOT / RWB)            // 49 invalid blocks

typedef unsigned long long u64;

// ---------------- device scratch (static; no cudaMalloc) ---------------------
__device__ __align__(16) u64 g_vkeys[NTOT];   // compacted valid keys (any order)
__device__ float4 g_box[NTOT];
__device__ float4 g_pay[NTOT];        // (score, label, keep, 0)
__device__ int g_cnt[BATCHN];         // valid count per batch
__device__ u64 g_vmask[BATCHN * 2];   // validity bitmask per batch (98 bits)
__device__ int g_vtotal;              // atomic compaction counter (memset to 0)

// sigmoid matching XLA-GPU exp-based logistic: 1/(1+__nv_expf(-x)), div.rn
__device__ __forceinline__ float sigmoidf(float x) {
    return 1.0f / (1.0f + expf(-x));
}

__device__ __forceinline__ unsigned f2sortable(float f) {
    unsigned b = __float_as_uint(f);
    return (b & 0x80000000u) ? ~b : (b | 0x80000000u);
}

// ============ A) fused decode + parallel local rank + NMS + compaction =======
__global__ void __launch_bounds__(256) decode_nms_kernel(const float* __restrict__ p) {
    __shared__ float s_dec[GS * GS * CH];        // 1470 decoded values
    __shared__ u64 s_key[PER_BATCH];
    __shared__ float4 s_nbox[PER_BATCH];
    __shared__ unsigned char s_nlab[PER_BATCH];
    __shared__ unsigned char s_nloc[PER_BATCH];
    __shared__ unsigned char s_keep[PER_BATCH];
    __shared__ __align__(16) unsigned s_adj[PER_BATCH][4];  // suppression rows
    __shared__ unsigned s_supw[4];
    __shared__ unsigned s_wb[4];
    __shared__ int s_cnt;
    __shared__ int s_base;

    int tid = threadIdx.x;
    int b = blockIdx.x;

    // Phase 0: cooperative sigmoid decode (w,h channels raw)
    const float* pb = p + (size_t)b * (GS * GS * CH);
    for (int i = tid; i < GS * GS * CH; i += 256) {
        int c = i % CH;
        float x = pb[i];
        bool raw = (c == 2) | (c == 3) | (c == 6) | (c == 7);
        s_dec[i] = raw ? x : sigmoidf(x);
    }
    if (tid < PER_BATCH) {
        s_adj[tid][0] = 0; s_adj[tid][1] = 0; s_adj[tid][2] = 0; s_adj[tid][3] = 0;
        s_keep[tid] = 0;
    }
    __syncthreads();

    // Phase 1: per-box decode (one thread per box)
    bool valid = false;
    u64 mykey = 0;
    float4 mybox;
    float myconf = 0.0f;
    unsigned char mylab = 0;
    if (tid < PER_BATCH) {
        int cell = tid >> 1;
        int bb = tid & 1;
        int gy = cell / GS, gx = cell % GS;
        const float* d = s_dec + cell * CH;

        float best = d[8 + NB + 0];
        int bi = 0;
#pragma unroll
        for (int c = 1; c < NC; c++) {
            float v = d[8 + NB + c];
            if (v > best) { best = v; bi = c; }
        }
        mylab = (unsigned char)(bi + 1);

        myconf = d[8 + bb];
        valid = myconf > 0.5f;
        float sx = d[bb * 4 + 0];
        float sy = d[bb * 4 + 1];
        float w = d[bb * 4 + 2];
        float h = d[bb * 4 + 3];
        float cx = (sx + (float)gx) / 7.0f;
        float cy = (sy + (float)gy) / 7.0f;
        mybox.x = cx - w / 2.0f;
        mybox.y = cy - h / 2.0f;
        mybox.z = cx + w / 2.0f;
        mybox.w = cy + h / 2.0f;

        int n = b * PER_BATCH + tid;
        g_box[n] = mybox;
        float keyf = valid ? myconf : __int_as_float(0xff800000);   // -inf
        mykey = ((u64)f2sortable(keyf) << 32) | (unsigned)n;
        s_key[tid] = mykey;
    }
    unsigned wb = __ballot_sync(0xffffffffu, valid);
    if ((tid & 31) == 0 && tid < 128) s_wb[tid >> 5] = wb;
    __syncthreads();
    if (tid == 0) {
        u64 m0 = (u64)s_wb[0] | ((u64)s_wb[1] << 32);
        u64 m1 = (u64)s_wb[2] | ((u64)s_wb[3] << 32);
        g_vmask[2 * b] = m0;
        g_vmask[2 * b + 1] = m1;
        int cnt = __popcll(m0) + __popcll(m1);
        s_cnt = cnt;
        g_cnt[b] = cnt;
        s_base = atomicAdd(&g_vtotal, cnt);
    }
    __syncthreads();

    // Phase 2: parallel local rank (valid keys outrank all invalid; keys unique)
    if (tid < PER_BATCH && valid) {
        int r = 0;
#pragma unroll 7
        for (int j = 0; j < PER_BATCH; j++)
            r += (s_key[j] > mykey);
        s_nbox[r] = mybox;
        s_nlab[r] = mylab;
        s_nloc[r] = (unsigned char)tid;
        g_vkeys[s_base + r] = mykey;
    }
    __syncthreads();

    int cnt = s_cnt;

    // Phase 3: parallel pairwise IoU -> adjacency bits (one j per thread per i)
    for (int i = 0; i < cnt - 1; i++) {
        int j = i + 1 + tid;
        if (j < cnt && s_nlab[i] == s_nlab[j]) {
            float4 bi = s_nbox[i];
            float4 bj = s_nbox[j];
            float ltx = fmaxf(bi.x, bj.x);
            float lty = fmaxf(bi.y, bj.y);
            float rbx = fminf(bi.z, bj.z);
            float rby = fminf(bi.w, bj.w);
            float iw = fmaxf(rbx - ltx, 0.0f);
            float ih = fmaxf(rby - lty, 0.0f);
            float inter = iw * ih;
            float ai = (bi.z - bi.x) * (bi.w - bi.y);
            float aj = (bj.z - bj.x) * (bj.w - bj.y);
            float uni = ai + aj - inter;
            float iou = inter / fmaxf(uni, 1e-9f);
            if (iou > THR_NMS)
                atomicOr(&s_adj[i][j >> 5], 1u << (j & 31));
        }
    }
    __syncthreads();

    // Phase 4: greedy scan, warp-parallel via register rows + shfl broadcast
    if (tid < 32) {
        int lane = tid;
        unsigned r00, r01, r02, r03;     // row lane
        unsigned r10, r11, r12, r13;     // row lane+32
        unsigned r20, r21, r22, r23;     // row lane+64  (<= 95 < 98, always safe)
        unsigned r30, r31, r32, r33;     // row lane+96  (only lanes 0,1)
        r00 = s_adj[lane][0]; r01 = s_adj[lane][1];
        r02 = s_adj[lane][2]; r03 = s_adj[lane][3];
        r10 = s_adj[lane + 32][0]; r11 = s_adj[lane + 32][1];
        r12 = s_adj[lane + 32][2]; r13 = s_adj[lane + 32][3];
        r20 = s_adj[lane + 64][0]; r21 = s_adj[lane + 64][1];
        r22 = s_adj[lane + 64][2]; r23 = s_adj[lane + 64][3];
        if (lane < 2) {
            r30 = s_adj[lane + 96][0]; r31 = s_adj[lane + 96][1];
            r32 = s_adj[lane + 96][2]; r33 = s_adj[lane + 96][3];
        } else { r30 = r31 = r32 = r33 = 0; }

        unsigned sup0 = 0, sup1 = 0, sup2 = 0, sup3 = 0;
        int c = cnt;
        int e0 = min(c, 32);
        for (int s = 0; s < e0; s++) {
            unsigned w0 = __shfl_sync(0xffffffffu, r00, s);
            unsigned w1 = __shfl_sync(0xffffffffu, r01, s);
            unsigned w2 = __shfl_sync(0xffffffffu, r02, s);
            unsigned w3 = __shfl_sync(0xffffffffu, r03, s);
            if (!((sup0 >> s) & 1u)) { sup0 |= w0; sup1 |= w1; sup2 |= w2; sup3 |= w3; }
        }
        int e1 = min(c - 32, 32);
        for (int s = 0; s < e1; s++) {
            unsigned w0 = __shfl_sync(0xffffffffu, r10, s);
            unsigned w1 = __shfl_sync(0xffffffffu, r11, s);
            unsigned w2 = __shfl_sync(0xffffffffu, r12, s);
            unsigned w3 = __shfl_sync(0xffffffffu, r13, s);
            if (!((sup1 >> s) & 1u)) { sup0 |= w0; sup1 |= w1; sup2 |= w2; sup3 |= w3; }
        }
        int e2 = min(c - 64, 32);
        for (int s = 0; s < e2; s++) {
            unsigned w0 = __shfl_sync(0xffffffffu, r20, s);
            unsigned w1 = __shfl_sync(0xffffffffu, r21, s);
            unsigned w2 = __shfl_sync(0xffffffffu, r22, s);
            unsigned w3 = __shfl_sync(0xffffffffu, r23, s);
            if (!((sup2 >> s) & 1u)) { sup0 |= w0; sup1 |= w1; sup2 |= w2; sup3 |= w3; }
        }
        int e3 = min(c - 96, 32);
        for (int s = 0; s < e3; s++) {
            unsigned w0 = __shfl_sync(0xffffffffu, r30, s);
            unsigned w1 = __shfl_sync(0xffffffffu, r31, s);
            unsigned w2 = __shfl_sync(0xffffffffu, r32, s);
            unsigned w3 = __shfl_sync(0xffffffffu, r33, s);
            if (!((sup3 >> s) & 1u)) { sup0 |= w0; sup1 |= w1; sup2 |= w2; sup3 |= w3; }
        }
        if (lane == 0) {
            s_supw[0] = sup0; s_supw[1] = sup1; s_supw[2] = sup2; s_supw[3] = sup3;
        }
    }
    __syncthreads();

    if (tid < cnt) {
        if (!((s_supw[tid >> 5] >> (tid & 31)) & 1u))
            s_keep[s_nloc[tid]] = 1;
    }
    __syncthreads();

    // Phase 5: payload write
    if (tid < PER_BATCH) {
        int n = b * PER_BATCH + tid;
        g_pay[n] = make_float4(myconf, (float)mylab,
                               s_keep[tid] ? 1.0f : 0.0f, 0.0f);
    }
}

// ============ B) fused valid-rank + invalid-write ============================
// blocks [0, NVBLK): warp-per-4-elements brute-force rank, no smem/barriers
// blocks [NVBLK, NVBLK+NIBLK): invalid elements, O(1) rank each
__global__ void __launch_bounds__(RWB) rank_write_kernel(float* __restrict__ out) {
    int blk = blockIdx.x;
    int tid = threadIdx.x;

    if (blk < NVBLK) {
        int V = g_vtotal;
        int gw = blk * 8 + (tid >> 5);      // global warp id
        int eBase = gw * ELW;
        if (eBase >= V) return;
        int lane = tid & 31;

        u64 mk0 = g_vkeys[min(eBase + 0, V - 1)];
        u64 mk1 = g_vkeys[min(eBase + 1, V - 1)];
        u64 mk2 = g_vkeys[min(eBase + 2, V - 1)];
        u64 mk3 = g_vkeys[min(eBase + 3, V - 1)];

        int c0 = 0, c1 = 0, c2 = 0, c3 = 0;
        int nv2 = V >> 1;
        const ulonglong2* vk2 = (const ulonglong2*)g_vkeys;
#pragma unroll 4
        for (int i2 = lane; i2 < nv2; i2 += 32) {
            ulonglong2 v = vk2[i2];
            c0 += (v.x > mk0) + (v.y > mk0);
            c1 += (v.x > mk1) + (v.y > mk1);
            c2 += (v.x > mk2) + (v.y > mk2);
            c3 += (v.x > mk3) + (v.y > mk3);
        }
        if ((V & 1) && lane == 0) {
            u64 v = g_vkeys[V - 1];
            c0 += (v > mk0); c1 += (v > mk1); c2 += (v > mk2); c3 += (v > mk3);
        }
#pragma unroll
        for (int d = 16; d >= 1; d >>= 1) {
            c0 += __shfl_xor_sync(0xffffffffu, c0, d);
            c1 += __shfl_xor_sync(0xffffffffu, c1, d);
            c2 += __shfl_xor_sync(0xffffffffu, c2, d);
            c3 += __shfl_xor_sync(0xffffffffu, c3, d);
        }
        if (lane < ELW && eBase + lane < V) {
            int rank;
            u64 mykey;
            switch (lane) {
                case 0: rank = c0; mykey = mk0; break;
                case 1: rank = c1; mykey = mk1; break;
                case 2: rank = c2; mykey = mk2; break;
                default: rank = c3; mykey = mk3; break;
            }
            unsigned idx = (unsigned)(mykey & 0xffffffffu);
            float4 bx = g_box[idx];
            float4 pay = g_pay[idx];
            out[rank] = (float)(idx / PER_BATCH);
            *(float4*)(out + NTOT + 4 * rank) = bx;
            out[5 * NTOT + rank] = pay.y;   // label
            out[6 * NTOT + rank] = pay.x;   // score
            out[7 * NTOT + rank] = pay.z;   // keep
        }
    } else {
        __shared__ int s_incl[BATCHN];
        __shared__ int s_ws[4];
        int lane = tid & 31;

        if (tid < BATCHN) {
            int x = g_cnt[tid];
#pragma unroll
            for (int d = 1; d < 32; d <<= 1) {
                int y = __shfl_up_sync(0xffffffffu, x, d);
                if (lane >= d) x += y;
            }
            if (lane == 31) s_ws[tid >> 5] = x;
            s_incl[tid] = x;
        }
        __syncthreads();
        if (tid == 0) {
            int a = 0;
#pragma unroll
            for (int w = 0; w < 4; w++) { int t = s_ws[w]; s_ws[w] = a; a += t; }
        }
        __syncthreads();
        if (tid < BATCHN) s_incl[tid] += s_ws[tid >> 5];
        __syncthreads();

        int V = s_incl[BATCHN - 1];
        int n = (blk - NVBLK) * RWB + tid;   // 49*256 == NTOT exactly
        int b = n / PER_BATCH;
        int local = n - b * PER_BATCH;
        u64 m0 = g_vmask[2 * b];
        u64 m1 = g_vmask[2 * b + 1];
        bool valid = (local < 64) ? ((m0 >> local) & 1ULL)
                                  : ((m1 >> (local - 64)) & 1ULL);
        if (valid) return;

        u64 i0 = ~m0;
        u64 i1 = (~m1) & ((1ULL << (PER_BATCH - 64)) - 1);
        int after;
        if (local < 64) {
            u64 hi = (local == 63) ? 0ULL : (i0 >> (local + 1));
            after = __popcll(hi) + __popcll(i1);
        } else {
            after = __popcll(i1 >> (local - 63));
        }
        int invafter = (NTOT - V) - (PER_BATCH * (b + 1) - s_incl[b]);
        int rank = V + invafter + after;

        float4 bx = g_box[n];
        float4 pay = g_pay[n];
        out[rank] = (float)b;
        *(float4*)(out + NTOT + 4 * rank) = bx;
        out[5 * NTOT + rank] = pay.y;
        out[6 * NTOT + rank] = pay.x;
        out[7 * NTOT + rank] = 0.0f;
    }
}

// ---------------- launch -----------------------------------------------------
extern "C" void kernel_launch(void* const* d_in, const int* in_sizes, int n_in,
                              void* d_out, int out_size) {
    const float* p = (const float*)d_in[0];
    float* out = (float*)d_out;

    void* vt = nullptr;
    cudaGetSymbolAddress(&vt, g_vtotal);
    cudaMemsetAsync(vt, 0, sizeof(int));

    decode_nms_kernel<<<BATCHN, 256>>>(p);
    rank_write_kernel<<<NVBLK + NIBLK, RWB>>>(out);
}

// round 9
// speedup vs baseline: 2.1388x; 1.4034x over previous
#include <cuda_runtime.h>
#include <cstdint>

// Problem constants
#define BATCHN 128
#define GS 7
#define NB 2
#define NC 20
#define CH 30
#define CELLS (BATCHN * GS * GS)      // 6272
#define NTOT (CELLS * NB)             // 12544
#define PER_BATCH (GS * GS * NB)      // 98
#define THR_NMS 0.3f

// rank kernel: 256-thread blocks; 16 elements/block; warps 0-3 stream half 0,
// warps 4-7 stream half 1 (4 elements per warp each)
#define RWB 256
#define EPB 16
#define NVBLK (NTOT / EPB)            // 784 valid blocks (worst case V = NTOT)
#define NIBLK (NTOT / RWB)            // 49 invalid blocks

typedef unsigned long long u64;

// ---------------- device scratch (static; no cudaMalloc) ---------------------
__device__ __align__(16) u64 g_vkeys[NTOT];   // compacted valid keys (any order)
__device__ float4 g_box[NTOT];
__device__ float4 g_pay[NTOT];        // (score, label, keep, 0)
__device__ int g_cnt[BATCHN];         // valid count per batch
__device__ u64 g_vmask[BATCHN * 2];   // validity bitmask per batch (98 bits)
__device__ int g_vtotal;              // atomic compaction counter (memset to 0)

// sigmoid matching XLA-GPU exp-based logistic: 1/(1+__nv_expf(-x)), div.rn
__device__ __forceinline__ float sigmoidf(float x) {
    return 1.0f / (1.0f + expf(-x));
}

__device__ __forceinline__ unsigned f2sortable(float f) {
    unsigned b = __float_as_uint(f);
    return (b & 0x80000000u) ? ~b : (b | 0x80000000u);
}

// ============ A) fused decode + parallel local rank + NMS + compaction =======
__global__ void __launch_bounds__(256) decode_nms_kernel(const float* __restrict__ p) {
    __shared__ float s_dec[GS * GS * CH];        // 1470 decoded values
    __shared__ u64 s_key[PER_BATCH];
    __shared__ float4 s_nbox[PER_BATCH];
    __shared__ unsigned char s_nlab[PER_BATCH];
    __shared__ unsigned char s_nloc[PER_BATCH];
    __shared__ unsigned char s_keep[PER_BATCH];
    __shared__ __align__(16) unsigned s_adj[PER_BATCH][4];  // suppression rows
    __shared__ unsigned s_supw[4];
    __shared__ unsigned s_wb[4];
    __shared__ int s_cnt;
    __shared__ int s_base;

    int tid = threadIdx.x;
    int b = blockIdx.x;

    // Phase 0: cooperative sigmoid decode (w,h channels raw)
    const float* pb = p + (size_t)b * (GS * GS * CH);
    for (int i = tid; i < GS * GS * CH; i += 256) {
        int c = i % CH;
        float x = pb[i];
        bool raw = (c == 2) | (c == 3) | (c == 6) | (c == 7);
        s_dec[i] = raw ? x : sigmoidf(x);
    }
    if (tid < PER_BATCH) {
        s_adj[tid][0] = 0; s_adj[tid][1] = 0; s_adj[tid][2] = 0; s_adj[tid][3] = 0;
        s_keep[tid] = 0;
    }
    __syncthreads();

    // Phase 1: per-box decode (one thread per box)
    bool valid = false;
    u64 mykey = 0;
    float4 mybox;
    float myconf = 0.0f;
    unsigned char mylab = 0;
    if (tid < PER_BATCH) {
        int cell = tid >> 1;
        int bb = tid & 1;
        int gy = cell / GS, gx = cell % GS;
        const float* d = s_dec + cell * CH;

        float best = d[8 + NB + 0];
        int bi = 0;
#pragma unroll
        for (int c = 1; c < NC; c++) {
            float v = d[8 + NB + c];
            if (v > best) { best = v; bi = c; }
        }
        mylab = (unsigned char)(bi + 1);

        myconf = d[8 + bb];
        valid = myconf > 0.5f;
        float sx = d[bb * 4 + 0];
        float sy = d[bb * 4 + 1];
        float w = d[bb * 4 + 2];
        float h = d[bb * 4 + 3];
        float cx = (sx + (float)gx) / 7.0f;
        float cy = (sy + (float)gy) / 7.0f;
        mybox.x = cx - w / 2.0f;
        mybox.y = cy - h / 2.0f;
        mybox.z = cx + w / 2.0f;
        mybox.w = cy + h / 2.0f;

        int n = b * PER_BATCH + tid;
        g_box[n] = mybox;
        float keyf = valid ? myconf : __int_as_float(0xff800000);   // -inf
        mykey = ((u64)f2sortable(keyf) << 32) | (unsigned)n;
        s_key[tid] = mykey;
    }
    unsigned wb = __ballot_sync(0xffffffffu, valid);
    if ((tid & 31) == 0 && tid < 128) s_wb[tid >> 5] = wb;
    __syncthreads();
    if (tid == 0) {
        u64 m0 = (u64)s_wb[0] | ((u64)s_wb[1] << 32);
        u64 m1 = (u64)s_wb[2] | ((u64)s_wb[3] << 32);
        g_vmask[2 * b] = m0;
        g_vmask[2 * b + 1] = m1;
        int cnt = __popcll(m0) + __popcll(m1);
        s_cnt = cnt;
        g_cnt[b] = cnt;
        s_base = atomicAdd(&g_vtotal, cnt);
    }
    __syncthreads();

    // Phase 2: parallel local rank (valid keys outrank all invalid; keys unique)
    if (tid < PER_BATCH && valid) {
        int r = 0;
#pragma unroll 7
        for (int j = 0; j < PER_BATCH; j++)
            r += (s_key[j] > mykey);
        s_nbox[r] = mybox;
        s_nlab[r] = mylab;
        s_nloc[r] = (unsigned char)tid;
        g_vkeys[s_base + r] = mykey;
    }
    __syncthreads();

    int cnt = s_cnt;

    // Phase 3: flattened triangular pairwise IoU -> adjacency bits
    {
        int P = cnt * (cnt - 1) / 2;
        for (int pp = tid; pp < P; pp += 256) {
            int s = P - 1 - pp;
            int k = (int)floorf((sqrtf(8.0f * (float)s + 1.0f) - 1.0f) * 0.5f);
            while ((k + 1) * (k + 2) / 2 <= s) k++;
            while (k * (k + 1) / 2 > s) k--;
            int o = s - k * (k + 1) / 2;
            int i = cnt - 2 - k;
            int j = cnt - 1 - o;
            if (s_nlab[i] == s_nlab[j]) {
                float4 bi = s_nbox[i];
                float4 bj = s_nbox[j];
                float ltx = fmaxf(bi.x, bj.x);
                float lty = fmaxf(bi.y, bj.y);
                float rbx = fminf(bi.z, bj.z);
                float rby = fminf(bi.w, bj.w);
                float iw = fmaxf(rbx - ltx, 0.0f);
                float ih = fmaxf(rby - lty, 0.0f);
                float inter = iw * ih;
                float ai = (bi.z - bi.x) * (bi.w - bi.y);
                float aj = (bj.z - bj.x) * (bj.w - bj.y);
                float uni = ai + aj - inter;
                float iou = inter / fmaxf(uni, 1e-9f);
                if (iou > THR_NMS)
                    atomicOr(&s_adj[i][j >> 5], 1u << (j & 31));
            }
        }
    }
    __syncthreads();

    // Phase 4: greedy scan, warp-parallel via register rows + shfl broadcast
    if (tid < 32) {
        int lane = tid;
        unsigned r00 = s_adj[lane][0],      r01 = s_adj[lane][1];
        unsigned r02 = s_adj[lane][2],      r03 = s_adj[lane][3];
        unsigned r10 = s_adj[lane + 32][0], r11 = s_adj[lane + 32][1];
        unsigned r12 = s_adj[lane + 32][2], r13 = s_adj[lane + 32][3];
        unsigned r20 = s_adj[lane + 64][0], r21 = s_adj[lane + 64][1];
        unsigned r22 = s_adj[lane + 64][2], r23 = s_adj[lane + 64][3];
        unsigned r30 = 0, r31 = 0, r32 = 0, r33 = 0;
        if (lane < 2) {
            r30 = s_adj[lane + 96][0]; r31 = s_adj[lane + 96][1];
            r32 = s_adj[lane + 96][2]; r33 = s_adj[lane + 96][3];
        }

        unsigned sup0 = 0, sup1 = 0, sup2 = 0, sup3 = 0;
        int c = cnt;
        int e0 = min(c, 32);
        for (int s = 0; s < e0; s++) {
            unsigned w0 = __shfl_sync(0xffffffffu, r00, s);
            unsigned w1 = __shfl_sync(0xffffffffu, r01, s);
            unsigned w2 = __shfl_sync(0xffffffffu, r02, s);
            unsigned w3 = __shfl_sync(0xffffffffu, r03, s);
            if (!((sup0 >> s) & 1u)) { sup0 |= w0; sup1 |= w1; sup2 |= w2; sup3 |= w3; }
        }
        int e1 = min(c - 32, 32);
        for (int s = 0; s < e1; s++) {
            unsigned w0 = __shfl_sync(0xffffffffu, r10, s);
            unsigned w1 = __shfl_sync(0xffffffffu, r11, s);
            unsigned w2 = __shfl_sync(0xffffffffu, r12, s);
            unsigned w3 = __shfl_sync(0xffffffffu, r13, s);
            if (!((sup1 >> s) & 1u)) { sup0 |= w0; sup1 |= w1; sup2 |= w2; sup3 |= w3; }
        }
        int e2 = min(c - 64, 32);
        for (int s = 0; s < e2; s++) {
            unsigned w0 = __shfl_sync(0xffffffffu, r20, s);
            unsigned w1 = __shfl_sync(0xffffffffu, r21, s);
            unsigned w2 = __shfl_sync(0xffffffffu, r22, s);
            unsigned w3 = __shfl_sync(0xffffffffu, r23, s);
            if (!((sup2 >> s) & 1u)) { sup0 |= w0; sup1 |= w1; sup2 |= w2; sup3 |= w3; }
        }
        int e3 = min(c - 96, 32);
        for (int s = 0; s < e3; s++) {
            unsigned w0 = __shfl_sync(0xffffffffu, r30, s);
            unsigned w1 = __shfl_sync(0xffffffffu, r31, s);
            unsigned w2 = __shfl_sync(0xffffffffu, r32, s);
            unsigned w3 = __shfl_sync(0xffffffffu, r33, s);
            if (!((sup3 >> s) & 1u)) { sup0 |= w0; sup1 |= w1; sup2 |= w2; sup3 |= w3; }
        }
        if (lane == 0) {
            s_supw[0] = sup0; s_supw[1] = sup1; s_supw[2] = sup2; s_supw[3] = sup3;
        }
    }
    __syncthreads();

    if (tid < cnt) {
        if (!((s_supw[tid >> 5] >> (tid & 31)) & 1u))
            s_keep[s_nloc[tid]] = 1;
    }
    __syncthreads();

    // Phase 5: payload write
    if (tid < PER_BATCH) {
        int n = b * PER_BATCH + tid;
        g_pay[n] = make_float4(myconf, (float)mylab,
                               s_keep[tid] ? 1.0f : 0.0f, 0.0f);
    }
}

// ============ B) fused valid-rank + invalid-write ============================
// blocks [0, NVBLK): 16 elements/block; warps 0-3 handle stream half 0,
// warps 4-7 handle stream half 1; partial counts combined in smem.
// blocks [NVBLK, NVBLK+NIBLK): invalid elements, O(1) rank each
__global__ void __launch_bounds__(RWB) rank_write_kernel(float* __restrict__ out) {
    int blk = blockIdx.x;
    int tid = threadIdx.x;

    if (blk < NVBLK) {
        int V = g_vtotal;
        int eBase = blk * EPB;
        if (eBase >= V) return;
        int wid = tid >> 5;
        int lane = tid & 31;
        int half = wid >> 2;               // 0 or 1
        int quad = wid & 3;                // element group within block
        int e0 = eBase + quad * 4;

        __shared__ int s_part[2][EPB];

        u64 mk0 = g_vkeys[min(e0 + 0, V - 1)];
        u64 mk1 = g_vkeys[min(e0 + 1, V - 1)];
        u64 mk2 = g_vkeys[min(e0 + 2, V - 1)];
        u64 mk3 = g_vkeys[min(e0 + 3, V - 1)];

        int nv2 = V >> 1;                  // ulonglong2 count
        int h0 = nv2 >> 1;                 // split point
        int lo = half ? h0 : 0;
        int hi = half ? nv2 : h0;

        int c0 = 0, c1 = 0, c2 = 0, c3 = 0;
        const ulonglong2* vk2 = (const ulonglong2*)g_vkeys;
#pragma unroll 4
        for (int i2 = lo + lane; i2 < hi; i2 += 32) {
            ulonglong2 v = vk2[i2];
            c0 += (v.x > mk0) + (v.y > mk0);
            c1 += (v.x > mk1) + (v.y > mk1);
            c2 += (v.x > mk2) + (v.y > mk2);
            c3 += (v.x > mk3) + (v.y > mk3);
        }
        if ((V & 1) && half == 1 && lane == 0) {   // odd tail key
            u64 v = g_vkeys[V - 1];
            c0 += (v > mk0); c1 += (v > mk1); c2 += (v > mk2); c3 += (v > mk3);
        }
#pragma unroll
        for (int d = 16; d >= 1; d >>= 1) {
            c0 += __shfl_xor_sync(0xffffffffu, c0, d);
            c1 += __shfl_xor_sync(0xffffffffu, c1, d);
            c2 += __shfl_xor_sync(0xffffffffu, c2, d);
            c3 += __shfl_xor_sync(0xffffffffu, c3, d);
        }
        if (lane == 0) {
            s_part[half][quad * 4 + 0] = c0;
            s_part[half][quad * 4 + 1] = c1;
            s_part[half][quad * 4 + 2] = c2;
            s_part[half][quad * 4 + 3] = c3;
        }
        __syncthreads();

        if (tid < EPB && eBase + tid < V) {
            int rank = s_part[0][tid] + s_part[1][tid];
            u64 mykey = g_vkeys[eBase + tid];
            unsigned idx = (unsigned)(mykey & 0xffffffffu);
            float4 bx = g_box[idx];
            float4 pay = g_pay[idx];
            out[rank] = (float)(idx / PER_BATCH);
            *(float4*)(out + NTOT + 4 * rank) = bx;
            out[5 * NTOT + rank] = pay.y;   // label
            out[6 * NTOT + rank] = pay.x;   // score
            out[7 * NTOT + rank] = pay.z;   // keep
        }
    } else {
        __shared__ int s_incl[BATCHN];
        __shared__ int s_ws[4];
        int lane = tid & 31;

        if (tid < BATCHN) {
            int x = g_cnt[tid];
#pragma unroll
            for (int d = 1; d < 32; d <<= 1) {
                int y = __shfl_up_sync(0xffffffffu, x, d);
                if (lane >= d) x += y;
            }
            if (lane == 31) s_ws[tid >> 5] = x;
            s_incl[tid] = x;
        }
        __syncthreads();
        if (tid == 0) {
            int a = 0;
#pragma unroll
            for (int w = 0; w < 4; w++) { int t = s_ws[w]; s_ws[w] = a; a += t; }
        }
        __syncthreads();
        if (tid < BATCHN) s_incl[tid] += s_ws[tid >> 5];
        __syncthreads();

        int V = s_incl[BATCHN - 1];
        int n = (blk - NVBLK) * RWB + tid;   // 49*256 == NTOT exactly
        int b = n / PER_BATCH;
        int local = n - b * PER_BATCH;
        u64 m0 = g_vmask[2 * b];
        u64 m1 = g_vmask[2 * b + 1];
        bool valid = (local < 64) ? ((m0 >> local) & 1ULL)
                                  : ((m1 >> (local - 64)) & 1ULL);
        if (valid) return;

        u64 i0 = ~m0;
        u64 i1 = (~m1) & ((1ULL << (PER_BATCH - 64)) - 1);
        int after;
        if (local < 64) {
            u64 hi = (local == 63) ? 0ULL : (i0 >> (local + 1));
            after = __popcll(hi) + __popcll(i1);
        } else {
            after = __popcll(i1 >> (local - 63));
        }
        int invafter = (NTOT - V) - (PER_BATCH * (b + 1) - s_incl[b]);
        int rank = V + invafter + after;

        float4 bx = g_box[n];
        float4 pay = g_pay[n];
        out[rank] = (float)b;
        *(float4*)(out + NTOT + 4 * rank) = bx;
        out[5 * NTOT + rank] = pay.y;
        out[6 * NTOT + rank] = pay.x;
        out[7 * NTOT + rank] = 0.0f;
    }
}

// ---------------- launch -----------------------------------------------------
extern "C" void kernel_launch(void* const* d_in, const int* in_sizes, int n_in,
                              void* d_out, int out_size) {
    const float* p = (const float*)d_in[0];
    float* out = (float*)d_out;

    void* vt = nullptr;
    cudaGetSymbolAddress(&vt, g_vtotal);
    cudaMemsetAsync(vt, 0, sizeof(int));

    decode_nms_kernel<<<BATCHN, 256>>>(p);
    rank_write_kernel<<<NVBLK + NIBLK, RWB>>>(out);
}